// round 14
// baseline (speedup 1.0000x reference)
#include <cuda_runtime.h>

// DWTExtractor: 2-level Haar DWT + bilinear 2x upsample of level-2 details.
// Input:  (32, 1, 1024, 1024) fp32 -> Output: (32, 6, 512, 512) fp32
//          [cH1, cV1, cD1, up(cH2), up(cV2), up(cD2)]
//
// R11 champion geometry (FROZEN: 256 thr, lb(256,6), 32x32 tile) + cp.async
// input staging to raise memory-level parallelism without register cost:
//   Stage:   72x72 input floats (the 18x18 level-2 cells' 4x4 patches, with
//            cell-granularity clamping == jax resize weight renorm) into smem
//            via cp.async.cg 16B ops -- ~5/thread, no dest regs, L1-bypassed,
//            all front-issued so each block exposes DRAM latency once.
//   Compute: identical to champion, but cells read their 4x4 patch from smem
//            (LDS, 29cyc) instead of gmem. Level-2 coeffs -> sH/sV/sD; central
//            16x16 cells emit 2x2 level-1 blocks -> gmem (float2 __stcs).
//   Part 3:  scalar separable bilinear (0.75/0.25), 4 outputs/thread,
//            float4 __stcs. (Vector-LDS variant measured slower; keep scalar.)

#define TS    32
#define H2_T  18
#define H2_S  19
#define IN_W  72          // staged tile edge (floats)
#define IN_S  76          // staged row stride (floats), 304B, 16B-aligned

__global__ __launch_bounds__(256, 6)
void dwt_fused_kernel(const float* __restrict__ in, float* __restrict__ out)
{
    __shared__ __align__(16) float sIn[IN_W * IN_S];
    __shared__ float sH[H2_T * H2_S];
    __shared__ float sV[H2_T * H2_S];
    __shared__ float sD[H2_T * H2_S];

    const int b   = blockIdx.z;
    const int oy0 = blockIdx.y * TS;
    const int ox0 = blockIdx.x * TS;
    const int tid = threadIdx.x;

    const float* __restrict__ inb  = in  + (size_t)b * 1024 * 1024;
    float* __restrict__       outb = out + (size_t)b * 6 * 512 * 512;

    const int r0g = oy0 >> 1;   // level-2 tile origin on the 256-grid
    const int c0g = ox0 >> 1;

    // ---- Stage: 72 rows x 18 float4-chunks = 1296 cp.async.cg 16B ops ----
    // Chunk (iy, ic): local cell row (iy>>2), clamped at cell granularity.
    #pragma unroll 1
    for (int idx = tid; idx < IN_W * (IN_W / 4); idx += 256) {
        const int iy = idx / (IN_W / 4);          // 0..71
        const int ic = idx - iy * (IN_W / 4);     // 0..17
        const int cell_r = min(max(r0g - 1 + (iy >> 2), 0), 255);
        const int cell_c = min(max(c0g - 1 + ic,        0), 255);
        const int src_row = 4 * cell_r + (iy & 3);

        const float* src = inb + (size_t)src_row * 1024 + 4 * cell_c;
        unsigned smem_dst = (unsigned)__cvta_generic_to_shared(
            sIn + iy * IN_S + 4 * ic);
        asm volatile("cp.async.cg.shared.global [%0], [%1], 16;"
                     :: "r"(smem_dst), "l"(src));
    }
    asm volatile("cp.async.commit_group;");
    asm volatile("cp.async.wait_group 0;");
    __syncthreads();

    // ---- Compute: level-2 (18x18) + level-1 (central 16x16), from smem ----
    #pragma unroll 1
    for (int i = tid; i < H2_T * H2_T; i += 256) {
        const int lr = i / H2_T;
        const int lc = i - lr * H2_T;
        const int rr = r0g - 1 + lr;              // for output indexing only
        const int cc = c0g - 1 + lc;

        const float* p = sIn + (4 * lr) * IN_S + 4 * lc;
        const float4 v0 = *(const float4*)(p);
        const float4 v1 = *(const float4*)(p + IN_S);
        const float4 v2 = *(const float4*)(p + 2 * IN_S);
        const float4 v3 = *(const float4*)(p + 3 * IN_S);

        // per-row horizontal sums/diffs
        const float s0l = v0.x + v0.y, d0l = v0.x - v0.y;
        const float s0r = v0.z + v0.w, d0r = v0.z - v0.w;
        const float s1l = v1.x + v1.y, d1l = v1.x - v1.y;
        const float s1r = v1.z + v1.w, d1r = v1.z - v1.w;
        const float s2l = v2.x + v2.y, d2l = v2.x - v2.y;
        const float s2r = v2.z + v2.w, d2r = v2.z - v2.w;
        const float s3l = v3.x + v3.y, d3l = v3.x - v3.y;
        const float s3r = v3.z + v3.w, d3r = v3.z - v3.w;

        // 2*cA1 quad
        const float a00 = s0l + s1l, a01 = s0r + s1r;
        const float a10 = s2l + s3l, a11 = s2r + s3r;

        // level-2 coeffs: 0.5 (haar) * 0.5 (cA1 factor folded) = 0.25
        sH[lr * H2_S + lc] = (a00 - a01 + a10 - a11) * 0.25f;
        sV[lr * H2_S + lc] = (a00 + a01 - a10 - a11) * 0.25f;
        sD[lr * H2_S + lc] = (a00 - a01 - a10 + a11) * 0.25f;

        // central cells: 2x2 level-1 detail block (rows 2rr, 2rr+1)
        if ((unsigned)(lr - 1) < 16u && (unsigned)(lc - 1) < 16u) {
            const float2 hT = make_float2((d0l + d1l) * 0.5f, (d0r + d1r) * 0.5f);
            const float2 vT = make_float2((s0l - s1l) * 0.5f, (s0r - s1r) * 0.5f);
            const float2 dT = make_float2((d0l - d1l) * 0.5f, (d0r - d1r) * 0.5f);
            const float2 hB = make_float2((d2l + d3l) * 0.5f, (d2r + d3r) * 0.5f);
            const float2 vB = make_float2((s2l - s3l) * 0.5f, (s2r - s3r) * 0.5f);
            const float2 dB = make_float2((d2l - d3l) * 0.5f, (d2r - d3r) * 0.5f);

            const size_t oT = (size_t)(2 * rr) * 256 + cc;   // float2 index
            const size_t oB = oT + 256;                      // next row
            float2* o2 = (float2*)outb;
            __stcs(o2 + 0 * 131072 + oT, hT);
            __stcs(o2 + 0 * 131072 + oB, hB);
            __stcs(o2 + 1 * 131072 + oT, vT);
            __stcs(o2 + 1 * 131072 + oB, vB);
            __stcs(o2 + 2 * 131072 + oT, dT);
            __stcs(o2 + 2 * 131072 + oB, dB);
        }
    }

    __syncthreads();

    // ---- Part 3: half-pixel bilinear 2x, 4 horizontally-adjacent outputs ----
    // out[2k] = 0.25*v[k-1]+0.75*v[k],  out[2k+1] = 0.75*v[k]+0.25*v[k+1]
    {
        const int i  = tid;            // 256 items, exactly one iteration
        const int y  = i >> 3;         // 0..31
        const int xq = i & 7;          // group of 4 cols
        const int ky = (y >> 1) + 1;   // local level-2 row of k
        const int ry0 = (y & 1) ? ky     : ky - 1;
        const int ry1 = (y & 1) ? ky + 1 : ky;
        const float wy0 = (y & 1) ? 0.75f : 0.25f;
        const float wy1 = 1.0f - wy0;

        const int cb = 2 * xq;         // local level-2 cols cb..cb+3 used
        const int A0 = ry0 * H2_S + cb;
        const int A1 = ry1 * H2_S + cb;

        float4 hv, vv, dv;
        {
            const float m0 = wy0 * sH[A0    ] + wy1 * sH[A1    ];
            const float m1 = wy0 * sH[A0 + 1] + wy1 * sH[A1 + 1];
            const float m2 = wy0 * sH[A0 + 2] + wy1 * sH[A1 + 2];
            const float m3 = wy0 * sH[A0 + 3] + wy1 * sH[A1 + 3];
            hv.x = 0.25f * m0 + 0.75f * m1;
            hv.y = 0.75f * m1 + 0.25f * m2;
            hv.z = 0.25f * m1 + 0.75f * m2;
            hv.w = 0.75f * m2 + 0.25f * m3;
        }
        {
            const float m0 = wy0 * sV[A0    ] + wy1 * sV[A1    ];
            const float m1 = wy0 * sV[A0 + 1] + wy1 * sV[A1 + 1];
            const float m2 = wy0 * sV[A0 + 2] + wy1 * sV[A1 + 2];
            const float m3 = wy0 * sV[A0 + 3] + wy1 * sV[A1 + 3];
            vv.x = 0.25f * m0 + 0.75f * m1;
            vv.y = 0.75f * m1 + 0.25f * m2;
            vv.z = 0.25f * m1 + 0.75f * m2;
            vv.w = 0.75f * m2 + 0.25f * m3;
        }
        {
            const float m0 = wy0 * sD[A0    ] + wy1 * sD[A1    ];
            const float m1 = wy0 * sD[A0 + 1] + wy1 * sD[A1 + 1];
            const float m2 = wy0 * sD[A0 + 2] + wy1 * sD[A1 + 2];
            const float m3 = wy0 * sD[A0 + 3] + wy1 * sD[A1 + 3];
            dv.x = 0.25f * m0 + 0.75f * m1;
            dv.y = 0.75f * m1 + 0.25f * m2;
            dv.z = 0.25f * m1 + 0.75f * m2;
            dv.w = 0.75f * m2 + 0.25f * m3;
        }

        const size_t o4 = ((size_t)(oy0 + y) * 512 + ox0 + 4 * xq) >> 2;
        __stcs((float4*)outb + 3 * 65536 + o4, hv);
        __stcs((float4*)outb + 4 * 65536 + o4, vv);
        __stcs((float4*)outb + 5 * 65536 + o4, dv);
    }
}

extern "C" void kernel_launch(void* const* d_in, const int* in_sizes, int n_in,
                              void* d_out, int out_size)
{
    const float* x = (const float*)d_in[0];
    float* out = (float*)d_out;
    dim3 grid(512 / TS, 512 / TS, 32);   // (16, 16, 32) = 8192 blocks
    dwt_fused_kernel<<<grid, 256>>>(x, out);
}

// round 15
// speedup vs baseline: 1.4571x; 1.4571x over previous
#include <cuda_runtime.h>

// DWTExtractor: 2-level Haar DWT + bilinear 2x upsample of level-2 details.
// Input:  (32, 1, 1024, 1024) fp32 -> Output: (32, 6, 512, 512) fp32
//          [cH1, cV1, cD1, up(cH2), up(cV2), up(cD2)]
//
// Champion R11 geometry (FROZEN: 256 thr, lb(256,6), 32x32 tile, merged loop,
// 4 x LDG.128/cell, scalar Part 3, __stcs) + address-math hoisting only:
//   - one base pointer per 4x4 patch (rows at +0/+256/+512/+768 float4s)
//   - per-channel output base pointers computed once per block
//   Merged phase: 18x18 level-2 grid (1-halo, clamped == jax resize weight
//     renormalization); central 16x16 cells also emit the 2x2 level-1 block.
//   (one __syncthreads)
//   Part 3: scalar separable half-pixel bilinear (0.75/0.25), 4 outputs per
//     thread, float4 streaming stores.

#define TS    32
#define H2_T  18
#define H2_S  19

__global__ __launch_bounds__(256, 6)
void dwt_fused_kernel(const float* __restrict__ in, float* __restrict__ out)
{
    __shared__ float sH[H2_T * H2_S];
    __shared__ float sV[H2_T * H2_S];
    __shared__ float sD[H2_T * H2_S];

    const int b   = blockIdx.z;
    const int oy0 = blockIdx.y * TS;
    const int ox0 = blockIdx.x * TS;
    const int tid = threadIdx.x;

    const float* __restrict__ inb  = in  + (size_t)b * 1024 * 1024;
    float* __restrict__       outb = out + (size_t)b * 6 * 512 * 512;

    // per-channel float2 output bases (level-1 channels 0..2)
    float2* const oH = (float2*)outb;
    float2* const oV = oH + 131072;
    float2* const oD = oV + 131072;

    // ---- Merged phase: level-2 (18x18 w/ halo) + level-1 (central 16x16) ----
    const int r0g = oy0 >> 1;   // level-2 tile origin on the 256-grid
    const int c0g = ox0 >> 1;
    #pragma unroll 1
    for (int i = tid; i < H2_T * H2_T; i += 256) {
        const int lr = i / H2_T;
        const int lc = i - lr * H2_T;
        const int rr = r0g - 1 + lr;
        const int cc = c0g - 1 + lc;
        const int r = min(max(rr, 0), 255);   // clamp only bites on halo cells
        const int c = min(max(cc, 0), 255);

        // one base pointer; rows are +256 float4s apart (1024 floats)
        const float4* p = (const float4*)(inb + (size_t)r * 4096) + c;
        const float4 v0 = p[0];
        const float4 v1 = p[256];
        const float4 v2 = p[512];
        const float4 v3 = p[768];

        // per-row horizontal sums/diffs
        const float s0l = v0.x + v0.y, d0l = v0.x - v0.y;
        const float s0r = v0.z + v0.w, d0r = v0.z - v0.w;
        const float s1l = v1.x + v1.y, d1l = v1.x - v1.y;
        const float s1r = v1.z + v1.w, d1r = v1.z - v1.w;
        const float s2l = v2.x + v2.y, d2l = v2.x - v2.y;
        const float s2r = v2.z + v2.w, d2r = v2.z - v2.w;
        const float s3l = v3.x + v3.y, d3l = v3.x - v3.y;
        const float s3r = v3.z + v3.w, d3r = v3.z - v3.w;

        // 2*cA1 quad
        const float a00 = s0l + s1l, a01 = s0r + s1r;
        const float a10 = s2l + s3l, a11 = s2r + s3r;

        // level-2 coeffs: 0.5 (haar) * 0.5 (cA1 factor folded) = 0.25
        sH[lr * H2_S + lc] = (a00 - a01 + a10 - a11) * 0.25f;
        sV[lr * H2_S + lc] = (a00 + a01 - a10 - a11) * 0.25f;
        sD[lr * H2_S + lc] = (a00 - a01 - a10 + a11) * 0.25f;

        // central cells: 2x2 level-1 detail block (rows 2rr,2rr+1; cols
        // 2cc,2cc+1 on the 512-grid). lr,lc in [1,16] <=> unclamped.
        if ((unsigned)(lr - 1) < 16u && (unsigned)(lc - 1) < 16u) {
            const float2 hT = make_float2((d0l + d1l) * 0.5f, (d0r + d1r) * 0.5f);
            const float2 vT = make_float2((s0l - s1l) * 0.5f, (s0r - s1r) * 0.5f);
            const float2 dT = make_float2((d0l - d1l) * 0.5f, (d0r - d1r) * 0.5f);
            const float2 hB = make_float2((d2l + d3l) * 0.5f, (d2r + d3r) * 0.5f);
            const float2 vB = make_float2((s2l - s3l) * 0.5f, (s2r - s3r) * 0.5f);
            const float2 dB = make_float2((d2l - d3l) * 0.5f, (d2r - d3r) * 0.5f);

            const int oT = rr * 512 + cc;        // float2 index (rr<256 -> fits int)
            const int oB = oT + 256;             // next output row
            __stcs(oH + oT, hT);
            __stcs(oH + oB, hB);
            __stcs(oV + oT, vT);
            __stcs(oV + oB, vB);
            __stcs(oD + oT, dT);
            __stcs(oD + oB, dB);
        }
    }

    __syncthreads();

    // ---- Part 3: half-pixel bilinear 2x, 4 horizontally-adjacent outputs ----
    // out[2k] = 0.25*v[k-1]+0.75*v[k],  out[2k+1] = 0.75*v[k]+0.25*v[k+1]
    {
        const int y  = tid >> 3;       // 0..31
        const int xq = tid & 7;        // group of 4 cols
        const int ky = (y >> 1) + 1;   // local level-2 row of k
        const int ry0 = (y & 1) ? ky     : ky - 1;
        const int ry1 = (y & 1) ? ky + 1 : ky;
        const float wy0 = (y & 1) ? 0.75f : 0.25f;
        const float wy1 = 1.0f - wy0;

        const int cb = 2 * xq;         // local level-2 cols cb..cb+3 used
        const int A0 = ry0 * H2_S + cb;
        const int A1 = ry1 * H2_S + cb;

        float4 hv, vv, dv;
        {
            const float m0 = wy0 * sH[A0    ] + wy1 * sH[A1    ];
            const float m1 = wy0 * sH[A0 + 1] + wy1 * sH[A1 + 1];
            const float m2 = wy0 * sH[A0 + 2] + wy1 * sH[A1 + 2];
            const float m3 = wy0 * sH[A0 + 3] + wy1 * sH[A1 + 3];
            hv.x = 0.25f * m0 + 0.75f * m1;
            hv.y = 0.75f * m1 + 0.25f * m2;
            hv.z = 0.25f * m1 + 0.75f * m2;
            hv.w = 0.75f * m2 + 0.25f * m3;
        }
        {
            const float m0 = wy0 * sV[A0    ] + wy1 * sV[A1    ];
            const float m1 = wy0 * sV[A0 + 1] + wy1 * sV[A1 + 1];
            const float m2 = wy0 * sV[A0 + 2] + wy1 * sV[A1 + 2];
            const float m3 = wy0 * sV[A0 + 3] + wy1 * sV[A1 + 3];
            vv.x = 0.25f * m0 + 0.75f * m1;
            vv.y = 0.75f * m1 + 0.25f * m2;
            vv.z = 0.25f * m1 + 0.75f * m2;
            vv.w = 0.75f * m2 + 0.25f * m3;
        }
        {
            const float m0 = wy0 * sD[A0    ] + wy1 * sD[A1    ];
            const float m1 = wy0 * sD[A0 + 1] + wy1 * sD[A1 + 1];
            const float m2 = wy0 * sD[A0 + 2] + wy1 * sD[A1 + 2];
            const float m3 = wy0 * sD[A0 + 3] + wy1 * sD[A1 + 3];
            dv.x = 0.25f * m0 + 0.75f * m1;
            dv.y = 0.75f * m1 + 0.25f * m2;
            dv.z = 0.25f * m1 + 0.75f * m2;
            dv.w = 0.75f * m2 + 0.25f * m3;
        }

        // float4 output bases for channels 3..5
        float4* const u0 = (float4*)outb + 3 * 65536;
        const int o4 = ((oy0 + y) * 512 + ox0 + 4 * xq) >> 2;
        __stcs(u0 + o4,             hv);
        __stcs(u0 + 65536 + o4,     vv);
        __stcs(u0 + 2 * 65536 + o4, dv);
    }
}

extern "C" void kernel_launch(void* const* d_in, const int* in_sizes, int n_in,
                              void* d_out, int out_size)
{
    const float* x = (const float*)d_in[0];
    float* out = (float*)d_out;
    dim3 grid(512 / TS, 512 / TS, 32);   // (16, 16, 32) = 8192 blocks
    dwt_fused_kernel<<<grid, 256>>>(x, out);
}

// round 16
// speedup vs baseline: 1.6195x; 1.1114x over previous
#include <cuda_runtime.h>

// DWTExtractor: 2-level Haar DWT + bilinear 2x upsample of level-2 details.
// Input:  (32, 1, 1024, 1024) fp32 -> Output: (32, 6, 512, 512) fp32
//          [cH1, cV1, cD1, up(cH2), up(cV2), up(cD2)]
//
// Champion geometry (FROZEN: 256 thr, lb(256,6), 32x32 tile, 4xLDG.128/cell,
// scalar Part 3, __stcs). Change vs R14: the 324 level-2 cells are split as
// 256 central (exactly 1/thread) + 68 halo (threads 0-67), with ALL loads
// (halo first, then central) issued before any compute -- removes the second
// exposed memory-latency round the old 2-iteration loop had. Halo computed
// first (its data arrives first; frees its registers early).
//   Halo clamping == jax resize weight renormalization at edges.
//   (one __syncthreads)
//   Part 3: scalar separable half-pixel bilinear (0.75/0.25), 4 outputs per
//   thread, float4 streaming stores.

#define TS    32
#define H2_T  18
#define H2_S  19

__global__ __launch_bounds__(256, 6)
void dwt_fused_kernel(const float* __restrict__ in, float* __restrict__ out)
{
    __shared__ float sH[H2_T * H2_S];
    __shared__ float sV[H2_T * H2_S];
    __shared__ float sD[H2_T * H2_S];

    const int b   = blockIdx.z;
    const int oy0 = blockIdx.y * TS;
    const int ox0 = blockIdx.x * TS;
    const int tid = threadIdx.x;

    const float* __restrict__ inb  = in  + (size_t)b * 1024 * 1024;
    float* __restrict__       outb = out + (size_t)b * 6 * 512 * 512;

    // per-channel float2 output bases (level-1 channels 0..2)
    float2* const oH = (float2*)outb;
    float2* const oV = oH + 131072;
    float2* const oD = oV + 131072;

    const int r0g = oy0 >> 1;   // level-2 tile origin on the 256-grid
    const int c0g = ox0 >> 1;

    // ---- Halo ring mapping (68 cells of the 18x18 grid) ----
    const bool has_halo = tid < 68;
    int hlr, hlc;
    if (tid < 18)       { hlr = 0;         hlc = tid;      }
    else if (tid < 36)  { hlr = 17;        hlc = tid - 18; }
    else if (tid < 52)  { hlr = tid - 35;  hlc = 0;        }
    else                { hlr = tid - 51;  hlc = 17;       }
    const int hr = min(max(r0g - 1 + hlr, 0), 255);   // clamp == jax renorm
    const int hc = min(max(c0g - 1 + hlc, 0), 255);

    // ---- Issue ALL loads up front: halo first, then central ----
    float4 h0, h1, h2, h3;
    if (has_halo) {
        const float4* hp = (const float4*)(inb + (size_t)hr * 4096) + hc;
        h0 = hp[0];  h1 = hp[256];  h2 = hp[512];  h3 = hp[768];
    }

    // central cell: exactly one per thread (16x16 grid)
    const int crow = tid >> 4;          // 0..15
    const int ccol = tid & 15;          // 0..15
    const int rr = r0g + crow;          // in range, no clamp
    const int cc = c0g + ccol;
    const float4* p = (const float4*)(inb + (size_t)rr * 4096) + cc;
    const float4 v0 = p[0];
    const float4 v1 = p[256];
    const float4 v2 = p[512];
    const float4 v3 = p[768];

    // ---- Halo compute first (data arrived first; frees registers) ----
    if (has_halo) {
        const float a00 = (h0.x + h0.y) + (h1.x + h1.y);
        const float a01 = (h0.z + h0.w) + (h1.z + h1.w);
        const float a10 = (h2.x + h2.y) + (h3.x + h3.y);
        const float a11 = (h2.z + h2.w) + (h3.z + h3.w);
        sH[hlr * H2_S + hlc] = (a00 - a01 + a10 - a11) * 0.25f;
        sV[hlr * H2_S + hlc] = (a00 + a01 - a10 - a11) * 0.25f;
        sD[hlr * H2_S + hlc] = (a00 - a01 - a10 + a11) * 0.25f;
    }

    // ---- Central compute: level-2 -> smem, level-1 2x2 block -> gmem ----
    {
        const float s0l = v0.x + v0.y, d0l = v0.x - v0.y;
        const float s0r = v0.z + v0.w, d0r = v0.z - v0.w;
        const float s1l = v1.x + v1.y, d1l = v1.x - v1.y;
        const float s1r = v1.z + v1.w, d1r = v1.z - v1.w;
        const float s2l = v2.x + v2.y, d2l = v2.x - v2.y;
        const float s2r = v2.z + v2.w, d2r = v2.z - v2.w;
        const float s3l = v3.x + v3.y, d3l = v3.x - v3.y;
        const float s3r = v3.z + v3.w, d3r = v3.z - v3.w;

        const float a00 = s0l + s1l, a01 = s0r + s1r;
        const float a10 = s2l + s3l, a11 = s2r + s3r;

        // level-2 coeffs: 0.5 (haar) * 0.5 (cA1 factor folded) = 0.25
        const int sidx = (crow + 1) * H2_S + (ccol + 1);
        sH[sidx] = (a00 - a01 + a10 - a11) * 0.25f;
        sV[sidx] = (a00 + a01 - a10 - a11) * 0.25f;
        sD[sidx] = (a00 - a01 - a10 + a11) * 0.25f;

        const float2 hT = make_float2((d0l + d1l) * 0.5f, (d0r + d1r) * 0.5f);
        const float2 vT = make_float2((s0l - s1l) * 0.5f, (s0r - s1r) * 0.5f);
        const float2 dT = make_float2((d0l - d1l) * 0.5f, (d0r - d1r) * 0.5f);
        const float2 hB = make_float2((d2l + d3l) * 0.5f, (d2r + d3r) * 0.5f);
        const float2 vB = make_float2((s2l - s3l) * 0.5f, (s2r - s3r) * 0.5f);
        const float2 dB = make_float2((d2l - d3l) * 0.5f, (d2r - d3r) * 0.5f);

        const int oT = rr * 512 + cc;        // float2 index
        const int oB = oT + 256;             // next output row
        __stcs(oH + oT, hT);
        __stcs(oH + oB, hB);
        __stcs(oV + oT, vT);
        __stcs(oV + oB, vB);
        __stcs(oD + oT, dT);
        __stcs(oD + oB, dB);
    }

    __syncthreads();

    // ---- Part 3: half-pixel bilinear 2x, 4 horizontally-adjacent outputs ----
    // out[2k] = 0.25*v[k-1]+0.75*v[k],  out[2k+1] = 0.75*v[k]+0.25*v[k+1]
    {
        const int y  = tid >> 3;       // 0..31
        const int xq = tid & 7;        // group of 4 cols
        const int ky = (y >> 1) + 1;   // local level-2 row of k
        const int ry0 = (y & 1) ? ky     : ky - 1;
        const int ry1 = (y & 1) ? ky + 1 : ky;
        const float wy0 = (y & 1) ? 0.75f : 0.25f;
        const float wy1 = 1.0f - wy0;

        const int cb = 2 * xq;         // local level-2 cols cb..cb+3 used
        const int A0 = ry0 * H2_S + cb;
        const int A1 = ry1 * H2_S + cb;

        float4 hv, vv, dv;
        {
            const float m0 = wy0 * sH[A0    ] + wy1 * sH[A1    ];
            const float m1 = wy0 * sH[A0 + 1] + wy1 * sH[A1 + 1];
            const float m2 = wy0 * sH[A0 + 2] + wy1 * sH[A1 + 2];
            const float m3 = wy0 * sH[A0 + 3] + wy1 * sH[A1 + 3];
            hv.x = 0.25f * m0 + 0.75f * m1;
            hv.y = 0.75f * m1 + 0.25f * m2;
            hv.z = 0.25f * m1 + 0.75f * m2;
            hv.w = 0.75f * m2 + 0.25f * m3;
        }
        {
            const float m0 = wy0 * sV[A0    ] + wy1 * sV[A1    ];
            const float m1 = wy0 * sV[A0 + 1] + wy1 * sV[A1 + 1];
            const float m2 = wy0 * sV[A0 + 2] + wy1 * sV[A1 + 2];
            const float m3 = wy0 * sV[A0 + 3] + wy1 * sV[A1 + 3];
            vv.x = 0.25f * m0 + 0.75f * m1;
            vv.y = 0.75f * m1 + 0.25f * m2;
            vv.z = 0.25f * m1 + 0.75f * m2;
            vv.w = 0.75f * m2 + 0.25f * m3;
        }
        {
            const float m0 = wy0 * sD[A0    ] + wy1 * sD[A1    ];
            const float m1 = wy0 * sD[A0 + 1] + wy1 * sD[A1 + 1];
            const float m2 = wy0 * sD[A0 + 2] + wy1 * sD[A1 + 2];
            const float m3 = wy0 * sD[A0 + 3] + wy1 * sD[A1 + 3];
            dv.x = 0.25f * m0 + 0.75f * m1;
            dv.y = 0.75f * m1 + 0.25f * m2;
            dv.z = 0.25f * m1 + 0.75f * m2;
            dv.w = 0.75f * m2 + 0.25f * m3;
        }

        float4* const u0 = (float4*)outb + 3 * 65536;
        const int o4 = ((oy0 + y) * 512 + ox0 + 4 * xq) >> 2;
        __stcs(u0 + o4,             hv);
        __stcs(u0 + 65536 + o4,     vv);
        __stcs(u0 + 2 * 65536 + o4, dv);
    }
}

extern "C" void kernel_launch(void* const* d_in, const int* in_sizes, int n_in,
                              void* d_out, int out_size)
{
    const float* x = (const float*)d_in[0];
    float* out = (float*)d_out;
    dim3 grid(512 / TS, 512 / TS, 32);   // (16, 16, 32) = 8192 blocks
    dwt_fused_kernel<<<grid, 256>>>(x, out);
}